// round 1
// baseline (speedup 1.0000x reference)
#include <cuda_runtime.h>
#include <cuda_bf16.h>
#include <math.h>

// Problem constants
#define BB 256      // batch
#define TT 128      // timesteps
#define HH 2048     // hidden
#define CC 10       // classes

// GEMM tiling
#define BM 64
#define BN 64
#define BK 16
#define TM 4
#define TN 4
#define NTHREADS 256

// Ping-pong hidden state (allocation-free scratch)
__device__ float g_h[2][BB * HH];

// ---------------------------------------------------------------------------
// Zero-init h0
// ---------------------------------------------------------------------------
__global__ void rnn_zero_kernel() {
    int i = blockIdx.x * blockDim.x + threadIdx.x;
    if (i < BB * HH) g_h[0][i] = 0.0f;
}

// ---------------------------------------------------------------------------
// One RNN step: h_out[b,j] = tanh( x[b,t]*U[j] + bh[j] + sum_k h_in[b,k]*W[j,k] )
// C = A * W^T  (A: [BB,HH] row-major, W: [HH,HH] row-major, K contiguous both)
// ---------------------------------------------------------------------------
__global__ __launch_bounds__(NTHREADS)
void rnn_step_kernel(const float* __restrict__ h_in,
                     float* __restrict__ h_out,
                     const float* __restrict__ x,
                     const float* __restrict__ U,
                     const float* __restrict__ W,
                     const float* __restrict__ bh,
                     int t) {
    __shared__ float As[BK][BM + 4];   // h tile, transposed (k-major)
    __shared__ float Bs[BK][BN + 4];   // W tile, transposed (k-major)

    const int bm = blockIdx.y * BM;    // batch offset
    const int bn = blockIdx.x * BN;    // hidden-out offset
    const int tid = threadIdx.x;
    const int tx = tid & 15;           // 0..15
    const int ty = tid >> 4;           // 0..15
    const int m0 = ty * TM;
    const int n0 = tx * TN;

    // Global-load mapping: each thread loads one float4 of A and one of B per k-tile
    const int lrow  = tid >> 2;        // 0..63
    const int lcol4 = (tid & 3) * 4;   // 0,4,8,12

    const float* Aptr = h_in + (size_t)(bm + lrow) * HH + lcol4;
    const float* Bptr = W    + (size_t)(bn + lrow) * HH + lcol4;

    float acc[TM][TN];
    #pragma unroll
    for (int i = 0; i < TM; i++)
        #pragma unroll
        for (int j = 0; j < TN; j++) acc[i][j] = 0.0f;

    for (int k0 = 0; k0 < HH; k0 += BK) {
        float4 a = *(const float4*)(Aptr + k0);
        float4 b = *(const float4*)(Bptr + k0);

        As[lcol4 + 0][lrow] = a.x;
        As[lcol4 + 1][lrow] = a.y;
        As[lcol4 + 2][lrow] = a.z;
        As[lcol4 + 3][lrow] = a.w;
        Bs[lcol4 + 0][lrow] = b.x;
        Bs[lcol4 + 1][lrow] = b.y;
        Bs[lcol4 + 2][lrow] = b.z;
        Bs[lcol4 + 3][lrow] = b.w;
        __syncthreads();

        #pragma unroll
        for (int k = 0; k < BK; k++) {
            float ra[TM], rb[TN];
            #pragma unroll
            for (int i = 0; i < TM; i++) ra[i] = As[k][m0 + i];
            #pragma unroll
            for (int j = 0; j < TN; j++) rb[j] = Bs[k][n0 + j];
            #pragma unroll
            for (int i = 0; i < TM; i++)
                #pragma unroll
                for (int j = 0; j < TN; j++)
                    acc[i][j] = fmaf(ra[i], rb[j], acc[i][j]);
        }
        __syncthreads();
    }

    // Epilogue: input injection + bias + tanh
    #pragma unroll
    for (int i = 0; i < TM; i++) {
        const int b = bm + m0 + i;
        const float xb = x[(size_t)b * TT + t];
        #pragma unroll
        for (int j = 0; j < TN; j++) {
            const int jj = bn + n0 + j;
            float v = acc[i][j] + xb * U[jj] + bh[jj];
            h_out[(size_t)b * HH + jj] = tanhf(v);
        }
    }
}

// ---------------------------------------------------------------------------
// Copy h_last -> d_out[0 : BB*HH]
// ---------------------------------------------------------------------------
__global__ void rnn_copy_kernel(const float* __restrict__ h, float* __restrict__ out) {
    int i = blockIdx.x * blockDim.x + threadIdx.x;
    int idx = i * 4;
    if (idx < BB * HH) {
        float4 v = *(const float4*)(h + idx);
        *(float4*)(out + idx) = v;
    }
}

// ---------------------------------------------------------------------------
// Head: out[b,c] = sum_k h[b,k]*V[c,k] + bp[c]   (C=10)
// one block per batch row
// ---------------------------------------------------------------------------
__global__ __launch_bounds__(256)
void rnn_head_kernel(const float* __restrict__ h,
                     const float* __restrict__ V,
                     const float* __restrict__ bp,
                     float* __restrict__ out) {
    const int b = blockIdx.x;
    const int tid = threadIdx.x;
    __shared__ float red[256];

    float partial[CC];
    #pragma unroll
    for (int c = 0; c < CC; c++) partial[c] = 0.0f;

    const float* hrow = h + (size_t)b * HH;
    for (int k = tid; k < HH; k += 256) {
        float hv = hrow[k];
        #pragma unroll
        for (int c = 0; c < CC; c++)
            partial[c] = fmaf(hv, V[(size_t)c * HH + k], partial[c]);
    }

    for (int c = 0; c < CC; c++) {
        red[tid] = partial[c];
        __syncthreads();
        for (int s = 128; s > 0; s >>= 1) {
            if (tid < s) red[tid] += red[tid + s];
            __syncthreads();
        }
        if (tid == 0) out[(size_t)b * CC + c] = red[0] + bp[c];
        __syncthreads();
    }
}

// ---------------------------------------------------------------------------
// Launch
// ---------------------------------------------------------------------------
extern "C" void kernel_launch(void* const* d_in, const int* in_sizes, int n_in,
                              void* d_out, int out_size) {
    const float* x  = (const float*)d_in[0];   // [B, T]
    const float* U  = (const float*)d_in[1];   // [H, 1]
    const float* W  = (const float*)d_in[2];   // [H, H]
    const float* V  = (const float*)d_in[3];   // [C, H]
    const float* bh = (const float*)d_in[4];   // [H]
    const float* bp = (const float*)d_in[5];   // [C]
    float* out = (float*)d_out;                // [B*H + B*C]

    float* hbuf0;
    float* hbuf1;
    cudaGetSymbolAddress((void**)&hbuf0, g_h);
    hbuf1 = hbuf0 + (size_t)BB * HH;

    // h0 = 0
    rnn_zero_kernel<<<(BB * HH + 255) / 256, 256>>>();

    // 128 sequential steps, ping-pong buffers
    dim3 grid(HH / BN, BB / BM);   // (32, 4) = 128 blocks
    for (int t = 0; t < TT; t++) {
        const float* hin = (t & 1) ? hbuf1 : hbuf0;
        float* hout      = (t & 1) ? hbuf0 : hbuf1;
        rnn_step_kernel<<<grid, NTHREADS>>>(hin, hout, x, U, W, bh, t);
    }

    // after T=128 steps, h_last is in buffer (128 & 1) == 0
    const float* hlast = hbuf0;

    rnn_copy_kernel<<<(BB * HH / 4 + 255) / 256, 256>>>(hlast, out);
    rnn_head_kernel<<<BB, 256>>>(hlast, V, bp, out + (size_t)BB * HH);
}

// round 3
// speedup vs baseline: 3.0894x; 3.0894x over previous
#include <cuda_runtime.h>
#include <cuda_bf16.h>
#include <math.h>
#include <stdint.h>

// ---------------------------------------------------------------------------
// Problem constants
// ---------------------------------------------------------------------------
#define BB 256      // batch
#define TT 128      // timesteps
#define HH 2048     // hidden
#define CC 10       // classes

// ---------------------------------------------------------------------------
// HMMA GEMM tiling: CTA 64x64, BK=32, 8 warps (2m x 4n), warp tile 32x16
// ---------------------------------------------------------------------------
#define BM 64
#define BN 64
#define BK 32
#define NKT (HH / BK)       // 64 k-iterations
#define NTH 256
#define ROWB 80             // smem row stride in bytes (32 bf16 + 8 pad = 40 bf16)

// smem: [2 stages][4 buffers][64 rows][40 bf16]; buffers: 0=Ahi 1=Alo 2=Whi 3=Wlo
#define STAGE_ROWS (4 * 64)

// ---------------------------------------------------------------------------
// Device-global scratch (allocation-free)
// ---------------------------------------------------------------------------
__device__ __nv_bfloat16 g_whi[HH * HH];
__device__ __nv_bfloat16 g_wlo[HH * HH];
__device__ __nv_bfloat16 g_hhi[2][BB * HH];
__device__ __nv_bfloat16 g_hlo[2][BB * HH];

// ---------------------------------------------------------------------------
// PTX helpers (base sm_80/sm_90 features only — NO 'a'-gated instructions)
// ---------------------------------------------------------------------------
__device__ __forceinline__ uint32_t smem_u32(const void* p) {
    uint32_t a;
    asm("{ .reg .u64 t; cvta.to.shared.u64 t, %1; cvt.u32.u64 %0, t; }"
        : "=r"(a) : "l"(p));
    return a;
}

__device__ __forceinline__ void cp16(uint32_t dst, const void* src) {
    asm volatile("cp.async.cg.shared.global [%0], [%1], 16;"
                 :: "r"(dst), "l"(src) : "memory");
}
__device__ __forceinline__ void cp_commit() {
    asm volatile("cp.async.commit_group;" ::: "memory");
}
__device__ __forceinline__ void cp_wait1() {
    asm volatile("cp.async.wait_group 1;" ::: "memory");
}
__device__ __forceinline__ void cp_wait0() {
    asm volatile("cp.async.wait_group 0;" ::: "memory");
}

__device__ __forceinline__ void ldsm4(uint32_t* r, uint32_t addr) {
    asm volatile("ldmatrix.sync.aligned.m8n8.x4.shared.b16 {%0,%1,%2,%3}, [%4];"
                 : "=r"(r[0]), "=r"(r[1]), "=r"(r[2]), "=r"(r[3]) : "r"(addr));
}

__device__ __forceinline__ void mma_bf16(float* c, const uint32_t* a, const uint32_t* b) {
    asm volatile(
        "mma.sync.aligned.m16n8k16.row.col.f32.bf16.bf16.f32 "
        "{%0,%1,%2,%3}, {%4,%5,%6,%7}, {%8,%9}, {%0,%1,%2,%3};"
        : "+f"(c[0]), "+f"(c[1]), "+f"(c[2]), "+f"(c[3])
        : "r"(a[0]), "r"(a[1]), "r"(a[2]), "r"(a[3]), "r"(b[0]), "r"(b[1]));
}

// ---------------------------------------------------------------------------
// Prep kernels
// ---------------------------------------------------------------------------
__global__ void k_convert_w(const float* __restrict__ W) {
    int i = blockIdx.x * blockDim.x + threadIdx.x;
    if (i < HH * HH) {
        float w = W[i];
        __nv_bfloat16 hi = __float2bfloat16(w);
        g_whi[i] = hi;
        g_wlo[i] = __float2bfloat16(w - __bfloat162float(hi));
    }
}

__global__ void k_init_h() {
    int i = blockIdx.x * blockDim.x + threadIdx.x;
    if (i < BB * HH) {
        g_hhi[0][i] = __float2bfloat16(0.0f);
        g_hlo[0][i] = __float2bfloat16(0.0f);
    }
}

// ---------------------------------------------------------------------------
// One RNN step: D = (hhi+hlo) @ (Whi+Wlo)^T  (3-term bf16 split on HMMA),
// epilogue: h_new = tanh(D + x[:,t]*U + bh), re-split to bf16 hi/lo
// ---------------------------------------------------------------------------
__global__ __launch_bounds__(NTH, 1)
void rnn_step_hmma(const __nv_bfloat16* __restrict__ hhi_in,
                   const __nv_bfloat16* __restrict__ hlo_in,
                   const float* __restrict__ x,
                   const float* __restrict__ U,
                   const float* __restrict__ bh,
                   __nv_bfloat16* __restrict__ hhi_out,
                   __nv_bfloat16* __restrict__ hlo_out,
                   float* __restrict__ fout,
                   int t, int is_last) {
    __shared__ __align__(128) __nv_bfloat16 sm[2][4][64][40];

    const uint32_t sbase = smem_u32(&sm[0][0][0][0]);
    const int tid  = threadIdx.x;
    const int wid  = tid >> 5;
    const int lane = tid & 31;
    const int n0 = blockIdx.x * BN;
    const int m0 = blockIdx.y * BM;

    const int wm = wid & 1;          // 0..1 -> 32-row group
    const int wn = wid >> 1;         // 0..3 -> 16-col group
    const int qid = lane >> 2;       // 0..7
    const int rid = lane & 3;        // 0..3

    // ---- cp.async mapping: 1 chunk (16B) per buffer per thread ----
    const int lrow = tid >> 2;       // 0..63
    const int lc4  = tid & 3;        // 0..3  -> 8-bf16 column group
    const __nv_bfloat16* gsrc[4];
    gsrc[0] = hhi_in + (size_t)(m0 + lrow) * HH + lc4 * 8;
    gsrc[1] = hlo_in + (size_t)(m0 + lrow) * HH + lc4 * 8;
    gsrc[2] = g_whi  + (size_t)(n0 + lrow) * HH + lc4 * 8;
    gsrc[3] = g_wlo  + (size_t)(n0 + lrow) * HH + lc4 * 8;
    // smem dst offsets (bytes), invariant except stage
    uint32_t sdst[4];
    #pragma unroll
    for (int bf = 0; bf < 4; bf++)
        sdst[bf] = sbase + (uint32_t)((bf * 64 + lrow) * ROWB + lc4 * 16);

    // ---- ldmatrix lane address components for A frags ----
    const int mrow_ld = (lane & 7) + 8 * ((lane >> 3) & 1);
    const int koff_ld = 8 * (lane >> 4);

    float acc[2][2][4];
    #pragma unroll
    for (int i = 0; i < 2; i++)
        #pragma unroll
        for (int j = 0; j < 2; j++)
            #pragma unroll
            for (int e = 0; e < 4; e++) acc[i][j][e] = 0.0f;

    // ---- prologue: load stage 0 ----
    #pragma unroll
    for (int bf = 0; bf < 4; bf++) cp16(sdst[bf], gsrc[bf]);
    cp_commit();

    const uint32_t stage_bytes = STAGE_ROWS * ROWB;

    for (int kt = 0; kt < NKT; kt++) {
        const int cur = kt & 1;
        if (kt + 1 < NKT) {
            const int nxt = (kt + 1) & 1;
            const int kk = (kt + 1) * BK;
            #pragma unroll
            for (int bf = 0; bf < 4; bf++)
                cp16(sdst[bf] + nxt * stage_bytes, gsrc[bf] + kk);
            cp_commit();
            cp_wait1();
        } else {
            cp_wait0();
        }
        __syncthreads();

        const uint32_t sb = sbase + cur * stage_bytes;
        #pragma unroll
        for (int kh = 0; kh < 2; kh++) {
            const int kc = kh * 16;
            // A fragments: 2 m16 tiles x (hi, lo)
            uint32_t ahi[2][4], alo[2][4];
            #pragma unroll
            for (int mt = 0; mt < 2; mt++) {
                const uint32_t arow = (uint32_t)(wm * 32 + mt * 16 + mrow_ld);
                const uint32_t acol = (uint32_t)(kc + koff_ld) * 2;
                ldsm4(ahi[mt], sb + (0 * 64 + arow) * ROWB + acol);
                ldsm4(alo[mt], sb + (1 * 64 + arow) * ROWB + acol);
            }
            // B fragments: 2 n8 tiles x (hi, lo), direct lds.32 (conflict-free)
            uint32_t bhi[2][2], blo[2][2];
            #pragma unroll
            for (int nt = 0; nt < 2; nt++) {
                const uint32_t brow = (uint32_t)(wn * 16 + nt * 8 + qid);
                const uint32_t bcol = (uint32_t)(kc + rid * 2) * 2;
                const uint32_t hioff = sb + (2 * 64 + brow) * ROWB + bcol;
                const uint32_t looff = sb + (3 * 64 + brow) * ROWB + bcol;
                asm volatile("ld.shared.b32 %0, [%1];" : "=r"(bhi[nt][0]) : "r"(hioff));
                asm volatile("ld.shared.b32 %0, [%1];" : "=r"(bhi[nt][1]) : "r"(hioff + 16));
                asm volatile("ld.shared.b32 %0, [%1];" : "=r"(blo[nt][0]) : "r"(looff));
                asm volatile("ld.shared.b32 %0, [%1];" : "=r"(blo[nt][1]) : "r"(looff + 16));
            }
            // 3-term MMA
            #pragma unroll
            for (int mt = 0; mt < 2; mt++)
                #pragma unroll
                for (int nt = 0; nt < 2; nt++) {
                    mma_bf16(acc[mt][nt], ahi[mt], bhi[nt]);
                    mma_bf16(acc[mt][nt], ahi[mt], blo[nt]);
                    mma_bf16(acc[mt][nt], alo[mt], bhi[nt]);
                }
        }
        __syncthreads();
    }

    // ---- epilogue: bias + input injection + tanh + bf16 hi/lo re-split ----
    #pragma unroll
    for (int mt = 0; mt < 2; mt++) {
        const int r0 = m0 + wm * 32 + mt * 16 + qid;
        const int r1 = r0 + 8;
        const float xb0 = x[(size_t)r0 * TT + t];
        const float xb1 = x[(size_t)r1 * TT + t];
        #pragma unroll
        for (int nt = 0; nt < 2; nt++) {
            const int j = n0 + wn * 16 + nt * 8 + rid * 2;
            const float u0 = U[j], u1 = U[j + 1];
            const float b0 = bh[j], b1 = bh[j + 1];

            float h00 = tanhf(acc[mt][nt][0] + xb0 * u0 + b0);
            float h01 = tanhf(acc[mt][nt][1] + xb0 * u1 + b1);
            float h10 = tanhf(acc[mt][nt][2] + xb1 * u0 + b0);
            float h11 = tanhf(acc[mt][nt][3] + xb1 * u1 + b1);

            #pragma unroll
            for (int rr = 0; rr < 2; rr++) {
                const int b = rr ? r1 : r0;
                const float v0 = rr ? h10 : h00;
                const float v1 = rr ? h11 : h01;
                __nv_bfloat16 hh0 = __float2bfloat16(v0);
                __nv_bfloat16 hh1 = __float2bfloat16(v1);
                __nv_bfloat16 ll0 = __float2bfloat16(v0 - __bfloat162float(hh0));
                __nv_bfloat16 ll1 = __float2bfloat16(v1 - __bfloat162float(hh1));
                unsigned short s0 = *(unsigned short*)&hh0;
                unsigned short s1 = *(unsigned short*)&hh1;
                unsigned short w0 = *(unsigned short*)&ll0;
                unsigned short w1 = *(unsigned short*)&ll1;
                *(uint32_t*)(hhi_out + (size_t)b * HH + j) = (uint32_t)s0 | ((uint32_t)s1 << 16);
                *(uint32_t*)(hlo_out + (size_t)b * HH + j) = (uint32_t)w0 | ((uint32_t)w1 << 16);
                if (is_last) {
                    fout[(size_t)b * HH + j]     = v0;
                    fout[(size_t)b * HH + j + 1] = v1;
                }
            }
        }
    }
}

// ---------------------------------------------------------------------------
// Head: out[b,c] = sum_k h[b,k]*V[c,k] + bp[c]
// ---------------------------------------------------------------------------
__global__ __launch_bounds__(256)
void rnn_head_kernel(const float* __restrict__ h,
                     const float* __restrict__ V,
                     const float* __restrict__ bp,
                     float* __restrict__ out) {
    const int b = blockIdx.x;
    const int tid = threadIdx.x;
    __shared__ float red[256];

    float partial[CC];
    #pragma unroll
    for (int c = 0; c < CC; c++) partial[c] = 0.0f;

    const float* hrow = h + (size_t)b * HH;
    for (int k = tid; k < HH; k += 256) {
        float hv = hrow[k];
        #pragma unroll
        for (int c = 0; c < CC; c++)
            partial[c] = fmaf(hv, V[(size_t)c * HH + k], partial[c]);
    }

    for (int c = 0; c < CC; c++) {
        red[tid] = partial[c];
        __syncthreads();
        for (int s = 128; s > 0; s >>= 1) {
            if (tid < s) red[tid] += red[tid + s];
            __syncthreads();
        }
        if (tid == 0) out[(size_t)b * CC + c] = red[0] + bp[c];
        __syncthreads();
    }
}

// ---------------------------------------------------------------------------
// Host launch
// ---------------------------------------------------------------------------
extern "C" void kernel_launch(void* const* d_in, const int* in_sizes, int n_in,
                              void* d_out, int out_size) {
    const float* x  = (const float*)d_in[0];   // [B, T]
    const float* U  = (const float*)d_in[1];   // [H, 1]
    const float* W  = (const float*)d_in[2];   // [H, H]
    const float* V  = (const float*)d_in[3];   // [C, H]
    const float* bh = (const float*)d_in[4];   // [H]
    const float* bp = (const float*)d_in[5];   // [C]
    float* out = (float*)d_out;                // [B*H + B*C]

    void *p_hhi, *p_hlo;
    cudaGetSymbolAddress(&p_hhi, g_hhi);
    cudaGetSymbolAddress(&p_hlo, g_hlo);
    __nv_bfloat16* hhi = (__nv_bfloat16*)p_hhi;
    __nv_bfloat16* hlo = (__nv_bfloat16*)p_hlo;

    // prep: split W into bf16 hi/lo, zero h0
    k_convert_w<<<(HH * HH + 255) / 256, 256>>>(W);
    k_init_h<<<(BB * HH + 255) / 256, 256>>>();

    // 128 sequential steps, ping-pong bf16 hidden state
    dim3 grid(HH / BN, BB / BM);  // (32, 4) = 128 CTAs
    for (int t = 0; t < TT; t++) {
        const int inb  = t & 1;
        const int outb = inb ^ 1;
        rnn_step_hmma<<<grid, NTH>>>(
            hhi + (size_t)inb * BB * HH,
            hlo + (size_t)inb * BB * HH,
            x, U, bh,
            hhi + (size_t)outb * BB * HH,
            hlo + (size_t)outb * BB * HH,
            out, t, (t == TT - 1) ? 1 : 0);
    }

    // head on fp32 h_last (written into d_out by last step)
    rnn_head_kernel<<<BB, 256>>>(out, V, bp, out + (size_t)BB * HH);
}

// round 4
// speedup vs baseline: 3.9107x; 1.2658x over previous
#include <cuda_runtime.h>
#include <cuda_bf16.h>
#include <math.h>
#include <stdint.h>

// ---------------------------------------------------------------------------
// Problem constants
// ---------------------------------------------------------------------------
#define BB 256      // batch
#define TT 128      // timesteps
#define HH 2048     // hidden
#define CC 10       // classes

// ---------------------------------------------------------------------------
// Tiling: CTA 64x64 output, 512 threads = 2 K-groups of 8 warps.
// Group g handles K in [g*1024, (g+1)*1024), BK=64, 16 k-iters, 2-stage pipe.
// Warp layout per group: 2m x 4n, warp tile 32x16.
// ---------------------------------------------------------------------------
#define BM 64
#define BN 64
#define BK 64
#define KSPLIT 1024
#define NKT (KSPLIT / BK)    // 16
#define NTH 512

#define ROWE 72              // smem row stride in bf16 elems (64 + 8 pad)
#define ROWB 144             // bytes
#define GSTAGE (4 * 64 * ROWB)          // one stage, one group: 36864 B
#define SMEM_TOTAL (2 * 2 * GSTAGE)     // 147456 B

// ---------------------------------------------------------------------------
// Device-global scratch (allocation-free)
// ---------------------------------------------------------------------------
__device__ __nv_bfloat16 g_whi[HH * HH];
__device__ __nv_bfloat16 g_wlo[HH * HH];
__device__ __nv_bfloat16 g_hhi[2][BB * HH];
__device__ __nv_bfloat16 g_hlo[2][BB * HH];

// ---------------------------------------------------------------------------
// PTX helpers (base-arch features only; nothing 'a'-gated)
// ---------------------------------------------------------------------------
__device__ __forceinline__ uint32_t smem_u32(const void* p) {
    uint32_t a;
    asm("{ .reg .u64 t; cvta.to.shared.u64 t, %1; cvt.u32.u64 %0, t; }"
        : "=r"(a) : "l"(p));
    return a;
}

__device__ __forceinline__ void cp16(uint32_t dst, const void* src) {
    asm volatile("cp.async.cg.shared.global [%0], [%1], 16;"
                 :: "r"(dst), "l"(src) : "memory");
}
__device__ __forceinline__ void cp_commit() {
    asm volatile("cp.async.commit_group;" ::: "memory");
}
__device__ __forceinline__ void cp_wait1() {
    asm volatile("cp.async.wait_group 1;" ::: "memory");
}
__device__ __forceinline__ void cp_wait0() {
    asm volatile("cp.async.wait_group 0;" ::: "memory");
}

__device__ __forceinline__ void barg(int id) {   // group barrier, 256 threads
    asm volatile("bar.sync %0, 256;" :: "r"(id) : "memory");
}
__device__ __forceinline__ void barall() {       // full CTA
    asm volatile("bar.sync 0, 512;" ::: "memory");
}

__device__ __forceinline__ void ldsm4(uint32_t* r, uint32_t addr) {
    asm volatile("ldmatrix.sync.aligned.m8n8.x4.shared.b16 {%0,%1,%2,%3}, [%4];"
                 : "=r"(r[0]), "=r"(r[1]), "=r"(r[2]), "=r"(r[3]) : "r"(addr));
}

__device__ __forceinline__ void mma_bf16(float* c, const uint32_t* a, const uint32_t* b) {
    asm volatile(
        "mma.sync.aligned.m16n8k16.row.col.f32.bf16.bf16.f32 "
        "{%0,%1,%2,%3}, {%4,%5,%6,%7}, {%8,%9}, {%0,%1,%2,%3};"
        : "+f"(c[0]), "+f"(c[1]), "+f"(c[2]), "+f"(c[3])
        : "r"(a[0]), "r"(a[1]), "r"(a[2]), "r"(a[3]), "r"(b[0]), "r"(b[1]));
}

// ---------------------------------------------------------------------------
// Prep kernels
// ---------------------------------------------------------------------------
__global__ void k_convert_w(const float* __restrict__ W) {
    int i = blockIdx.x * blockDim.x + threadIdx.x;
    if (i < HH * HH) {
        float w = W[i];
        __nv_bfloat16 hi = __float2bfloat16(w);
        g_whi[i] = hi;
        g_wlo[i] = __float2bfloat16(w - __bfloat162float(hi));
    }
}

__global__ void k_init_h() {
    int i = blockIdx.x * blockDim.x + threadIdx.x;
    if (i < BB * HH) {
        g_hhi[0][i] = __float2bfloat16(0.0f);
        g_hlo[0][i] = __float2bfloat16(0.0f);
    }
}

// ---------------------------------------------------------------------------
// One RNN step: D = (hhi+hlo) @ (Whi+Wlo)^T  (3-term bf16 split on HMMA)
// 2 K-groups in one CTA, independent pipelines + named barriers, smem combine.
// Epilogue: h_new = tanh(D + x[:,t]*U + bh), re-split to bf16 hi/lo.
// ---------------------------------------------------------------------------
__global__ __launch_bounds__(NTH, 1)
void rnn_step_hmma(const __nv_bfloat16* __restrict__ hhi_in,
                   const __nv_bfloat16* __restrict__ hlo_in,
                   const float* __restrict__ x,
                   const float* __restrict__ U,
                   const float* __restrict__ bh,
                   __nv_bfloat16* __restrict__ hhi_out,
                   __nv_bfloat16* __restrict__ hlo_out,
                   float* __restrict__ fout,
                   int t, int is_last) {
    extern __shared__ __align__(128) char smem[];
    const uint32_t sbase = smem_u32(smem);

    const int tid  = threadIdx.x;
    const int wid  = tid >> 5;
    const int lane = tid & 31;
    const int grp  = wid >> 3;           // 0 or 1 (K-group)
    const int gwid = wid & 7;            // warp id within group
    const int gtid = tid & 255;          // thread id within group
    const int n0 = blockIdx.x * BN;
    const int m0 = blockIdx.y * BM;

    const int wm = gwid & 1;             // 0..1 -> 32-row group
    const int wn = gwid >> 1;            // 0..3 -> 16-col group
    const int qid = lane >> 2;           // 0..7
    const int rid = lane & 3;            // 0..3

    const uint32_t gbase = sbase + (uint32_t)grp * (2 * GSTAGE);
    const int kbase = grp * KSPLIT;

    // ---- cp.async mapping: per buffer 64 rows x 8 chunks(16B); 2 chunks/thread
    const int c0 = gtid;                 // chunk ids c0, c0+256
    const int r0c = c0 >> 3, r1c = (c0 + 256) >> 3;
    const int col0 = (c0 & 7) * 8;       // bf16 offset within BK
    // col for second chunk = same (c&7) pattern
    const int col1 = ((c0 + 256) & 7) * 8;

    const __nv_bfloat16* gA0[2];  // chunk0: [hi, lo]
    const __nv_bfloat16* gA1[2];
    const __nv_bfloat16* gB0[2];
    const __nv_bfloat16* gB1[2];
    gA0[0] = hhi_in + (size_t)(m0 + r0c) * HH + kbase + col0;
    gA0[1] = hlo_in + (size_t)(m0 + r0c) * HH + kbase + col0;
    gA1[0] = hhi_in + (size_t)(m0 + r1c) * HH + kbase + col1;
    gA1[1] = hlo_in + (size_t)(m0 + r1c) * HH + kbase + col1;
    gB0[0] = g_whi  + (size_t)(n0 + r0c) * HH + kbase + col0;
    gB0[1] = g_wlo  + (size_t)(n0 + r0c) * HH + kbase + col0;
    gB1[0] = g_whi  + (size_t)(n0 + r1c) * HH + kbase + col1;
    gB1[1] = g_wlo  + (size_t)(n0 + r1c) * HH + kbase + col1;

    uint32_t d0[4], d1[4];   // smem dsts for chunk0/1 for bufs 0..3 (stage 0)
    #pragma unroll
    for (int bf = 0; bf < 4; bf++) {
        d0[bf] = gbase + (uint32_t)((bf * 64 + r0c) * ROWB + (col0 >> 3) * 16);
        d1[bf] = gbase + (uint32_t)((bf * 64 + r1c) * ROWB + (col1 >> 3) * 16);
    }

    // ---- ldmatrix lane addressing ----
    // A (row-major m16k16): lanes 0-7 rows+0 @k, 8-15 rows+8 @k, 16-23 rows+0 @k+8, 24-31 rows+8 @k+8
    const int a_row = (lane & 7) + 8 * ((lane >> 3) & 1);
    const int a_k   = 8 * (lane >> 4);
    // B (two n8 tiles per x4): lanes 0-7 n+0..7 @k, 8-15 n+0..7 @k+8, 16-23 n+8..15 @k, 24-31 n+8..15 @k+8
    const int b_row = ((lane >> 4) << 3) + (lane & 7);
    const int b_k   = ((lane >> 3) & 1) * 8;

    float acc[2][2][4];
    #pragma unroll
    for (int i = 0; i < 2; i++)
        #pragma unroll
        for (int j = 0; j < 2; j++)
            #pragma unroll
            for (int e = 0; e < 4; e++) acc[i][j][e] = 0.0f;

    // ---- prologue: stage 0 ----
    #pragma unroll
    for (int bf = 0; bf < 2; bf++) { cp16(d0[bf], gA0[bf]); cp16(d1[bf], gA1[bf]); }
    #pragma unroll
    for (int bf = 0; bf < 2; bf++) { cp16(d0[2 + bf], gB0[bf]); cp16(d1[2 + bf], gB1[bf]); }
    cp_commit();

    const int mybar = grp + 1;

    for (int kt = 0; kt < NKT; kt++) {
        const int cur = kt & 1;
        if (kt + 1 < NKT) {
            const uint32_t so = (uint32_t)((kt + 1) & 1) * GSTAGE;
            const int kk = (kt + 1) * BK;
            #pragma unroll
            for (int bf = 0; bf < 2; bf++) {
                cp16(d0[bf] + so, gA0[bf] + kk);
                cp16(d1[bf] + so, gA1[bf] + kk);
                cp16(d0[2 + bf] + so, gB0[bf] + kk);
                cp16(d1[2 + bf] + so, gB1[bf] + kk);
            }
            cp_commit();
            cp_wait1();
        } else {
            cp_wait0();
        }
        barg(mybar);

        const uint32_t sb = gbase + (uint32_t)cur * GSTAGE;
        #pragma unroll
        for (int kh = 0; kh < BK / 16; kh++) {
            const int kc = kh * 16;
            uint32_t ahi[2][4], alo[2][4];
            #pragma unroll
            for (int mt = 0; mt < 2; mt++) {
                const uint32_t arow = (uint32_t)(wm * 32 + mt * 16 + a_row);
                const uint32_t acol = (uint32_t)(kc + a_k) * 2;
                ldsm4(ahi[mt], sb + (0 * 64 + arow) * ROWB + acol);
                ldsm4(alo[mt], sb + (1 * 64 + arow) * ROWB + acol);
            }
            uint32_t bhi[4], blo[4];
            {
                const uint32_t brow = (uint32_t)(wn * 16 + b_row);
                const uint32_t bcol = (uint32_t)(kc + b_k) * 2;
                ldsm4(bhi, sb + (2 * 64 + brow) * ROWB + bcol);
                ldsm4(blo, sb + (3 * 64 + brow) * ROWB + bcol);
            }
            #pragma unroll
            for (int mt = 0; mt < 2; mt++)
                #pragma unroll
                for (int nt = 0; nt < 2; nt++) {
                    mma_bf16(acc[mt][nt], ahi[mt], bhi + 2 * nt);
                    mma_bf16(acc[mt][nt], ahi[mt], blo + 2 * nt);
                    mma_bf16(acc[mt][nt], alo[mt], bhi + 2 * nt);
                }
        }
        barg(mybar);
    }

    // ---- combine group 1 into group 0 via smem ----
    // exchange buffer: group 1's stage-0 region (free after its loop)
    float* ex = (float*)(smem + 2 * GSTAGE);
    if (grp == 1) {
        #pragma unroll
        for (int mt = 0; mt < 2; mt++)
            #pragma unroll
            for (int nt = 0; nt < 2; nt++)
                #pragma unroll
                for (int e = 0; e < 4; e++)
                    ex[(((gwid * 4 + mt * 2 + nt) * 4) + e) * 32 + lane] = acc[mt][nt][e];
    }
    barall();

    if (grp == 0) {
        #pragma unroll
        for (int mt = 0; mt < 2; mt++)
            #pragma unroll
            for (int nt = 0; nt < 2; nt++)
                #pragma unroll
                for (int e = 0; e < 4; e++)
                    acc[mt][nt][e] += ex[(((gwid * 4 + mt * 2 + nt) * 4) + e) * 32 + lane];

        // ---- epilogue: bias + input injection + tanh + bf16 hi/lo re-split ----
        #pragma unroll
        for (int mt = 0; mt < 2; mt++) {
            const int row0 = m0 + wm * 32 + mt * 16 + qid;
            const int row1 = row0 + 8;
            const float xb0 = x[(size_t)row0 * TT + t];
            const float xb1 = x[(size_t)row1 * TT + t];
            #pragma unroll
            for (int nt = 0; nt < 2; nt++) {
                const int j = n0 + wn * 16 + nt * 8 + rid * 2;
                const float u0 = U[j], u1 = U[j + 1];
                const float bb0 = bh[j], bb1 = bh[j + 1];

                float h00 = tanhf(acc[mt][nt][0] + xb0 * u0 + bb0);
                float h01 = tanhf(acc[mt][nt][1] + xb0 * u1 + bb1);
                float h10 = tanhf(acc[mt][nt][2] + xb1 * u0 + bb0);
                float h11 = tanhf(acc[mt][nt][3] + xb1 * u1 + bb1);

                #pragma unroll
                for (int rr = 0; rr < 2; rr++) {
                    const int b = rr ? row1 : row0;
                    const float v0 = rr ? h10 : h00;
                    const float v1 = rr ? h11 : h01;
                    __nv_bfloat16 hh0 = __float2bfloat16(v0);
                    __nv_bfloat16 hh1 = __float2bfloat16(v1);
                    __nv_bfloat16 ll0 = __float2bfloat16(v0 - __bfloat162float(hh0));
                    __nv_bfloat16 ll1 = __float2bfloat16(v1 - __bfloat162float(hh1));
                    unsigned short s0 = *(unsigned short*)&hh0;
                    unsigned short s1 = *(unsigned short*)&hh1;
                    unsigned short w0 = *(unsigned short*)&ll0;
                    unsigned short w1 = *(unsigned short*)&ll1;
                    *(uint32_t*)(hhi_out + (size_t)b * HH + j) = (uint32_t)s0 | ((uint32_t)s1 << 16);
                    *(uint32_t*)(hlo_out + (size_t)b * HH + j) = (uint32_t)w0 | ((uint32_t)w1 << 16);
                    if (is_last) {
                        fout[(size_t)b * HH + j]     = v0;
                        fout[(size_t)b * HH + j + 1] = v1;
                    }
                }
            }
        }
    }
}

// ---------------------------------------------------------------------------
// Head: out[b,c] = sum_k h[b,k]*V[c,k] + bp[c]
// ---------------------------------------------------------------------------
__global__ __launch_bounds__(256)
void rnn_head_kernel(const float* __restrict__ h,
                     const float* __restrict__ V,
                     const float* __restrict__ bp,
                     float* __restrict__ out) {
    const int b = blockIdx.x;
    const int tid = threadIdx.x;
    __shared__ float red[256];

    float partial[CC];
    #pragma unroll
    for (int c = 0; c < CC; c++) partial[c] = 0.0f;

    const float* hrow = h + (size_t)b * HH;
    for (int k = tid; k < HH; k += 256) {
        float hv = hrow[k];
        #pragma unroll
        for (int c = 0; c < CC; c++)
            partial[c] = fmaf(hv, V[(size_t)c * HH + k], partial[c]);
    }

    for (int c = 0; c < CC; c++) {
        red[tid] = partial[c];
        __syncthreads();
        for (int s = 128; s > 0; s >>= 1) {
            if (tid < s) red[tid] += red[tid + s];
            __syncthreads();
        }
        if (tid == 0) out[(size_t)b * CC + c] = red[0] + bp[c];
        __syncthreads();
    }
}

// ---------------------------------------------------------------------------
// Host launch
// ---------------------------------------------------------------------------
extern "C" void kernel_launch(void* const* d_in, const int* in_sizes, int n_in,
                              void* d_out, int out_size) {
    const float* x  = (const float*)d_in[0];   // [B, T]
    const float* U  = (const float*)d_in[1];   // [H, 1]
    const float* W  = (const float*)d_in[2];   // [H, H]
    const float* V  = (const float*)d_in[3];   // [C, H]
    const float* bh = (const float*)d_in[4];   // [H]
    const float* bp = (const float*)d_in[5];   // [C]
    float* out = (float*)d_out;                // [B*H + B*C]

    static int attr_set = 0;
    if (!attr_set) {
        cudaFuncSetAttribute(rnn_step_hmma,
                             cudaFuncAttributeMaxDynamicSharedMemorySize, SMEM_TOTAL);
        attr_set = 1;
    }

    void *p_hhi, *p_hlo;
    cudaGetSymbolAddress(&p_hhi, g_hhi);
    cudaGetSymbolAddress(&p_hlo, g_hlo);
    __nv_bfloat16* hhi = (__nv_bfloat16*)p_hhi;
    __nv_bfloat16* hlo = (__nv_bfloat16*)p_hlo;

    // prep: split W into bf16 hi/lo, zero h0
    k_convert_w<<<(HH * HH + 255) / 256, 256>>>(W);
    k_init_h<<<(BB * HH + 255) / 256, 256>>>();

    // 128 sequential steps, ping-pong bf16 hidden state
    dim3 grid(HH / BN, BB / BM);  // (32, 4) = 128 CTAs
    for (int t = 0; t < TT; t++) {
        const int inb  = t & 1;
        const int outb = inb ^ 1;
        rnn_step_hmma<<<grid, NTH, SMEM_TOTAL>>>(
            hhi + (size_t)inb * BB * HH,
            hlo + (size_t)inb * BB * HH,
            x, U, bh,
            hhi + (size_t)outb * BB * HH,
            hlo + (size_t)outb * BB * HH,
            out, t, (t == TT - 1) ? 1 : 0);
    }

    // head on fp32 h_last (written into d_out by last step)
    rnn_head_kernel<<<BB, 256>>>(out, V, bp, out + (size_t)BB * HH);
}

// round 5
// speedup vs baseline: 4.3117x; 1.1026x over previous
#include <cuda_runtime.h>
#include <cuda_bf16.h>
#include <math.h>
#include <stdint.h>

// ---------------------------------------------------------------------------
// Problem constants
// ---------------------------------------------------------------------------
#define BB 256      // batch
#define TT 128      // timesteps
#define HH 2048     // hidden
#define CC 10       // classes

// ---------------------------------------------------------------------------
// Tiling: CTA 64x64 output, 512 threads = 4 K-groups of 4 warps.
// Group g (warps 4g..4g+3) handles K in [g*512, (g+1)*512), BK=32, 16 k-iters,
// 2-stage cp.async pipe per group. Warp layout per group: 2m x 2n, tile 32x32.
// Warp w of group g sits on SMSP (4g+w)%4 == w -> one warp/group/SMSP.
// ---------------------------------------------------------------------------
#define BM 64
#define BN 64
#define BK 32
#define NGRP 4
#define KSPLIT (HH / NGRP)   // 512
#define NKT (KSPLIT / BK)    // 16
#define NTH 512

#define ROWB 80                          // 32 bf16 + 8 pad = 40 bf16 = 80 B
#define BUFB (64 * ROWB)                 // one 64-row buffer: 5120 B
#define GSTAGE (4 * BUFB)                // 4 buffers (Ahi,Alo,Whi,Wlo): 20480 B
#define GPIPE (2 * GSTAGE)               // 2 stages: 40960 B
#define EX_OFF (NGRP * GPIPE)            // 163840
#define EX_FLOATS (32 * 384)             // 32 values x (3 groups x 128 threads)
#define SMEM_TOTAL (EX_OFF + EX_FLOATS * 4)   // 212992 B

// ---------------------------------------------------------------------------
// Device-global scratch (allocation-free)
// ---------------------------------------------------------------------------
__device__ __nv_bfloat16 g_whi[HH * HH];
__device__ __nv_bfloat16 g_wlo[HH * HH];
__device__ __nv_bfloat16 g_hhi[2][BB * HH];
__device__ __nv_bfloat16 g_hlo[2][BB * HH];

// ---------------------------------------------------------------------------
// PTX helpers (base-arch features only; nothing 'a'-gated)
// ---------------------------------------------------------------------------
__device__ __forceinline__ uint32_t smem_u32(const void* p) {
    uint32_t a;
    asm("{ .reg .u64 t; cvta.to.shared.u64 t, %1; cvt.u32.u64 %0, t; }"
        : "=r"(a) : "l"(p));
    return a;
}

__device__ __forceinline__ void cp16(uint32_t dst, const void* src) {
    asm volatile("cp.async.cg.shared.global [%0], [%1], 16;"
                 :: "r"(dst), "l"(src) : "memory");
}
__device__ __forceinline__ void cp_commit() {
    asm volatile("cp.async.commit_group;" ::: "memory");
}
__device__ __forceinline__ void cp_wait1() {
    asm volatile("cp.async.wait_group 1;" ::: "memory");
}
__device__ __forceinline__ void cp_wait0() {
    asm volatile("cp.async.wait_group 0;" ::: "memory");
}

__device__ __forceinline__ void barg(int id) {   // per-group barrier, 128 thr
    asm volatile("bar.sync %0, 128;" :: "r"(id) : "memory");
}
__device__ __forceinline__ void barall() {       // full CTA
    asm volatile("bar.sync 0, 512;" ::: "memory");
}

__device__ __forceinline__ void ldsm4(uint32_t* r, uint32_t addr) {
    asm volatile("ldmatrix.sync.aligned.m8n8.x4.shared.b16 {%0,%1,%2,%3}, [%4];"
                 : "=r"(r[0]), "=r"(r[1]), "=r"(r[2]), "=r"(r[3]) : "r"(addr));
}

__device__ __forceinline__ void mma_bf16(float* c, const uint32_t* a, const uint32_t* b) {
    asm volatile(
        "mma.sync.aligned.m16n8k16.row.col.f32.bf16.bf16.f32 "
        "{%0,%1,%2,%3}, {%4,%5,%6,%7}, {%8,%9}, {%0,%1,%2,%3};"
        : "+f"(c[0]), "+f"(c[1]), "+f"(c[2]), "+f"(c[3])
        : "r"(a[0]), "r"(a[1]), "r"(a[2]), "r"(a[3]), "r"(b[0]), "r"(b[1]));
}

// ---------------------------------------------------------------------------
// Prep kernels
// ---------------------------------------------------------------------------
__global__ void k_convert_w(const float* __restrict__ W) {
    int i = blockIdx.x * blockDim.x + threadIdx.x;
    if (i < HH * HH) {
        float w = W[i];
        __nv_bfloat16 hi = __float2bfloat16(w);
        g_whi[i] = hi;
        g_wlo[i] = __float2bfloat16(w - __bfloat162float(hi));
    }
}

__global__ void k_init_h() {
    int i = blockIdx.x * blockDim.x + threadIdx.x;
    if (i < BB * HH) {
        g_hhi[0][i] = __float2bfloat16(0.0f);
        g_hlo[0][i] = __float2bfloat16(0.0f);
    }
}

// ---------------------------------------------------------------------------
// One RNN step: D = (hhi+hlo) @ (Whi+Wlo)^T  (3-term bf16 split on HMMA)
// 4 K-groups, independent pipelines + named barriers, smem combine.
// Epilogue: h_new = tanh(D + x[:,t]*U + bh), re-split to bf16 hi/lo.
// ---------------------------------------------------------------------------
__global__ __launch_bounds__(NTH, 1)
void rnn_step_hmma(const __nv_bfloat16* __restrict__ hhi_in,
                   const __nv_bfloat16* __restrict__ hlo_in,
                   const float* __restrict__ x,
                   const float* __restrict__ U,
                   const float* __restrict__ bh,
                   __nv_bfloat16* __restrict__ hhi_out,
                   __nv_bfloat16* __restrict__ hlo_out,
                   float* __restrict__ fout,
                   int t, int is_last) {
    extern __shared__ __align__(128) char smem[];
    const uint32_t sbase = smem_u32(smem);

    const int tid  = threadIdx.x;
    const int wid  = tid >> 5;
    const int lane = tid & 31;
    const int grp  = tid >> 7;           // 0..3 (K-group), == wid>>2
    const int gwid = wid & 3;            // warp id within group
    const int gtid = tid & 127;          // thread id within group
    const int n0 = blockIdx.x * BN;
    const int m0 = blockIdx.y * BM;

    const int wm = gwid & 1;             // 0..1 -> 32-row half
    const int wn = gwid >> 1;            // 0..1 -> 32-col half
    const int qid = lane >> 2;           // 0..7
    const int rid = lane & 3;            // 0..3

    const uint32_t gbase = sbase + (uint32_t)grp * GPIPE;
    const int kbase = grp * KSPLIT;

    // ---- cp.async mapping: per buffer, thread loads rows r0 and r0+32,
    //      16B chunk at column (gtid&3)*8 bf16. 4 bufs x 2 rows = 8 cp/thread.
    const int r0   = gtid >> 2;          // 0..31
    const int cbf  = (gtid & 3) * 8;     // bf16 col offset
    const int cby  = (gtid & 3) * 16;    // byte col offset

    const __nv_bfloat16* gsrc[4];        // row r0 pointers; +32*HH for row r0+32
    gsrc[0] = hhi_in + (size_t)(m0 + r0) * HH + kbase + cbf;
    gsrc[1] = hlo_in + (size_t)(m0 + r0) * HH + kbase + cbf;
    gsrc[2] = g_whi  + (size_t)(n0 + r0) * HH + kbase + cbf;
    gsrc[3] = g_wlo  + (size_t)(n0 + r0) * HH + kbase + cbf;

    uint32_t sdst[4];                    // stage-0 dsts for row r0
    #pragma unroll
    for (int bf = 0; bf < 4; bf++)
        sdst[bf] = gbase + (uint32_t)(bf * BUFB + r0 * ROWB + cby);

    // ---- ldmatrix lane addressing (identical formulas to R4, verified) ----
    const int a_row = (lane & 7) + 8 * ((lane >> 3) & 1);
    const int a_k   = 8 * (lane >> 4);
    const int b_row = ((lane >> 4) << 3) + (lane & 7);
    const int b_k   = ((lane >> 3) & 1) * 8;

    float acc[2][4][4];                  // [mt][n8 tile][elem]
    #pragma unroll
    for (int i = 0; i < 2; i++)
        #pragma unroll
        for (int j = 0; j < 4; j++)
            #pragma unroll
            for (int e = 0; e < 4; e++) acc[i][j][e] = 0.0f;

    // ---- prologue: stage 0 ----
    #pragma unroll
    for (int bf = 0; bf < 4; bf++) {
        cp16(sdst[bf],                 gsrc[bf]);
        cp16(sdst[bf] + 32 * ROWB,     gsrc[bf] + (size_t)32 * HH);
    }
    cp_commit();

    const int mybar = grp + 1;           // named barriers 1..4

    for (int kt = 0; kt < NKT; kt++) {
        const int cur = kt & 1;
        if (kt + 1 < NKT) {
            const uint32_t so = (uint32_t)((kt + 1) & 1) * GSTAGE;
            const int kk = (kt + 1) * BK;
            #pragma unroll
            for (int bf = 0; bf < 4; bf++) {
                cp16(sdst[bf] + so,             gsrc[bf] + kk);
                cp16(sdst[bf] + so + 32 * ROWB, gsrc[bf] + kk + (size_t)32 * HH);
            }
            cp_commit();
            cp_wait1();
        } else {
            cp_wait0();
        }
        barg(mybar);

        const uint32_t sb = gbase + (uint32_t)cur * GSTAGE;
        #pragma unroll
        for (int kh = 0; kh < BK / 16; kh++) {
            const int kc = kh * 16;
            // A fragments: 2 m16 tiles x (hi, lo)
            uint32_t ahi[2][4], alo[2][4];
            #pragma unroll
            for (int mt = 0; mt < 2; mt++) {
                const uint32_t arow = (uint32_t)(wm * 32 + mt * 16 + a_row);
                const uint32_t acol = (uint32_t)(kc + a_k) * 2;
                ldsm4(ahi[mt], sb + (0 * BUFB) + arow * ROWB + acol);
                ldsm4(alo[mt], sb + (1 * BUFB) + arow * ROWB + acol);
            }
            // B fragments: 32 cols = 4 n8 tiles, hi + lo (2 ldsm4 each)
            uint32_t bhi[8], blo[8];
            {
                const uint32_t brow = (uint32_t)(wn * 32 + b_row);
                const uint32_t bcol = (uint32_t)(kc + b_k) * 2;
                ldsm4(bhi,     sb + (2 * BUFB) + brow * ROWB + bcol);
                ldsm4(bhi + 4, sb + (2 * BUFB) + (brow + 16) * ROWB + bcol);
                ldsm4(blo,     sb + (3 * BUFB) + brow * ROWB + bcol);
                ldsm4(blo + 4, sb + (3 * BUFB) + (brow + 16) * ROWB + bcol);
            }
            // 3-term MMA: 2 mt x 4 n8 x 3 = 24 MMAs per kh
            #pragma unroll
            for (int mt = 0; mt < 2; mt++)
                #pragma unroll
                for (int nt = 0; nt < 4; nt++) {
                    mma_bf16(acc[mt][nt], ahi[mt], bhi + 2 * nt);
                    mma_bf16(acc[mt][nt], ahi[mt], blo + 2 * nt);
                    mma_bf16(acc[mt][nt], alo[mt], bhi + 2 * nt);
                }
        }
        barg(mybar);
    }

    // ---- combine groups 1..3 into group 0 via smem (conflict-free layout) ----
    float* ex = (float*)(smem + EX_OFF);
    if (grp != 0) {
        #pragma unroll
        for (int mt = 0; mt < 2; mt++)
            #pragma unroll
            for (int nt = 0; nt < 4; nt++)
                #pragma unroll
                for (int e = 0; e < 4; e++) {
                    const int v = (mt * 4 + nt) * 4 + e;
                    ex[v * 384 + (grp - 1) * 128 + gtid] = acc[mt][nt][e];
                }
    }
    barall();

    if (grp == 0) {
        #pragma unroll
        for (int mt = 0; mt < 2; mt++)
            #pragma unroll
            for (int nt = 0; nt < 4; nt++)
                #pragma unroll
                for (int e = 0; e < 4; e++) {
                    const int v = (mt * 4 + nt) * 4 + e;
                    acc[mt][nt][e] += ex[v * 384 + 0 * 128 + gtid]
                                    + ex[v * 384 + 1 * 128 + gtid]
                                    + ex[v * 384 + 2 * 128 + gtid];
                }

        // ---- epilogue: bias + input injection + tanh + bf16 hi/lo re-split ----
        #pragma unroll
        for (int mt = 0; mt < 2; mt++) {
            const int row0 = m0 + wm * 32 + mt * 16 + qid;
            const int row1 = row0 + 8;
            const float xb0 = x[(size_t)row0 * TT + t];
            const float xb1 = x[(size_t)row1 * TT + t];
            #pragma unroll
            for (int nt = 0; nt < 4; nt++) {
                const int j = n0 + wn * 32 + nt * 8 + rid * 2;
                const float u0 = U[j], u1 = U[j + 1];
                const float bb0 = bh[j], bb1 = bh[j + 1];

                float h00 = tanhf(acc[mt][nt][0] + xb0 * u0 + bb0);
                float h01 = tanhf(acc[mt][nt][1] + xb0 * u1 + bb1);
                float h10 = tanhf(acc[mt][nt][2] + xb1 * u0 + bb0);
                float h11 = tanhf(acc[mt][nt][3] + xb1 * u1 + bb1);

                #pragma unroll
                for (int rr = 0; rr < 2; rr++) {
                    const int b = rr ? row1 : row0;
                    const float v0 = rr ? h10 : h00;
                    const float v1 = rr ? h11 : h01;
                    __nv_bfloat16 hh0 = __float2bfloat16(v0);
                    __nv_bfloat16 hh1 = __float2bfloat16(v1);
                    __nv_bfloat16 ll0 = __float2bfloat16(v0 - __bfloat162float(hh0));
                    __nv_bfloat16 ll1 = __float2bfloat16(v1 - __bfloat162float(hh1));
                    unsigned short s0 = *(unsigned short*)&hh0;
                    unsigned short s1 = *(unsigned short*)&hh1;
                    unsigned short w0 = *(unsigned short*)&ll0;
                    unsigned short w1 = *(unsigned short*)&ll1;
                    *(uint32_t*)(hhi_out + (size_t)b * HH + j) = (uint32_t)s0 | ((uint32_t)s1 << 16);
                    *(uint32_t*)(hlo_out + (size_t)b * HH + j) = (uint32_t)w0 | ((uint32_t)w1 << 16);
                    if (is_last) {
                        fout[(size_t)b * HH + j]     = v0;
                        fout[(size_t)b * HH + j + 1] = v1;
                    }
                }
            }
        }
    }
}

// ---------------------------------------------------------------------------
// Head: out[b,c] = sum_k h[b,k]*V[c,k] + bp[c]
// ---------------------------------------------------------------------------
__global__ __launch_bounds__(256)
void rnn_head_kernel(const float* __restrict__ h,
                     const float* __restrict__ V,
                     const float* __restrict__ bp,
                     float* __restrict__ out) {
    const int b = blockIdx.x;
    const int tid = threadIdx.x;
    __shared__ float red[256];

    float partial[CC];
    #pragma unroll
    for (int c = 0; c < CC; c++) partial[c] = 0.0f;

    const float* hrow = h + (size_t)b * HH;
    for (int k = tid; k < HH; k += 256) {
        float hv = hrow[k];
        #pragma unroll
        for (int c = 0; c < CC; c++)
            partial[c] = fmaf(hv, V[(size_t)c * HH + k], partial[c]);
    }

    for (int c = 0; c < CC; c++) {
        red[tid] = partial[c];
        __syncthreads();
        for (int s = 128; s > 0; s >>= 1) {
            if (tid < s) red[tid] += red[tid + s];
            __syncthreads();
        }
        if (tid == 0) out[(size_t)b * CC + c] = red[0] + bp[c];
        __syncthreads();
    }
}

// ---------------------------------------------------------------------------
// Host launch
// ---------------------------------------------------------------------------
extern "C" void kernel_launch(void* const* d_in, const int* in_sizes, int n_in,
                              void* d_out, int out_size) {
    const float* x  = (const float*)d_in[0];   // [B, T]
    const float* U  = (const float*)d_in[1];   // [H, 1]
    const float* W  = (const float*)d_in[2];   // [H, H]
    const float* V  = (const float*)d_in[3];   // [C, H]
    const float* bh = (const float*)d_in[4];   // [H]
    const float* bp = (const float*)d_in[5];   // [C]
    float* out = (float*)d_out;                // [B*H + B*C]

    cudaFuncSetAttribute(rnn_step_hmma,
                         cudaFuncAttributeMaxDynamicSharedMemorySize, SMEM_TOTAL);

    void *p_hhi, *p_hlo;
    cudaGetSymbolAddress(&p_hhi, g_hhi);
    cudaGetSymbolAddress(&p_hlo, g_hlo);
    __nv_bfloat16* hhi = (__nv_bfloat16*)p_hhi;
    __nv_bfloat16* hlo = (__nv_bfloat16*)p_hlo;

    // prep: split W into bf16 hi/lo, zero h0
    k_convert_w<<<(HH * HH + 255) / 256, 256>>>(W);
    k_init_h<<<(BB * HH + 255) / 256, 256>>>();

    // 128 sequential steps, ping-pong bf16 hidden state
    dim3 grid(HH / BN, BB / BM);  // (32, 4) = 128 CTAs
    for (int t = 0; t < TT; t++) {
        const int inb  = t & 1;
        const int outb = inb ^ 1;
        rnn_step_hmma<<<grid, NTH, SMEM_TOTAL>>>(
            hhi + (size_t)inb * BB * HH,
            hlo + (size_t)inb * BB * HH,
            x, U, bh,
            hhi + (size_t)outb * BB * HH,
            hlo + (size_t)outb * BB * HH,
            out, t, (t == TT - 1) ? 1 : 0);
    }

    // head on fp32 h_last (written into d_out by last step)
    rnn_head_kernel<<<BB, 256>>>(out, V, bp, out + (size_t)BB * HH);
}